// round 10
// baseline (speedup 1.0000x reference)
#include <cuda_runtime.h>
#include <cuda_fp16.h>
#include <cstdint>
#include <cstddef>

// ScalarWaveletRecombiner: out[n,o] = W2[o]·silu(W1[o]·x[n] + b1[o]) + b2[o]
// x:[NC,64] W1:[32,128,64] b1:[32,128] W2:[32,128] b2:[32] -> out:[NC,32]
//
// v6: fp16 m16n8k16, m32n64 warp tile processed as 2x n32 chunks (32 live acc),
//   256-thread CTAs, __launch_bounds__(256,3) -> 3 CTAs/SM (24 warps/SM) to hide
//   MUFU/LDSM latency while keeping R8's HMMA-per-LDSM ratio.
//   smem [k-chunk][row][16B], conflict-free ldmatrix, no swizzle.

#define KDIM 64
#define HDIM 128
#define ODIM 32
#define OPB 2
#define ROWS 128
#define THREADS 256

// smem layout (bytes)
#define XS_OFF    0         // fp16 x  [8 kc][128 rows][16B] = 16384
#define WS_OFF    16384     // fp16 W1 [8 kc][256 rows][16B] = 32768
#define BW_OFF    49152     // float2 (0.5*b1, w2) [2][128]  = 2048
#define PART_OFF  51200     // float [2 ol][2 cg][128 rows]  = 2048
#define SMEM_BYTES 53248

#define XCHUNK 2048         // 128 rows * 16B
#define WCHUNK 4096         // 256 rows * 16B

__device__ __forceinline__ unsigned pack_f16x2(float lo, float hi) {
    unsigned r;
    asm("cvt.rn.f16x2.f32 %0, %2, %1;" : "=r"(r) : "f"(lo), "f"(hi));
    return r;
}

__device__ __forceinline__ uint32_t smem_u32(const void* p) {
    uint32_t a;
    asm("{ .reg .u64 t; cvta.to.shared.u64 t, %1; cvt.u32.u64 %0, t; }" : "=r"(a) : "l"(p));
    return a;
}

__device__ __forceinline__ void ldsm4(uint32_t addr, unsigned* r) {
    asm volatile("ldmatrix.sync.aligned.m8n8.x4.shared.b16 {%0,%1,%2,%3}, [%4];"
                 : "=r"(r[0]), "=r"(r[1]), "=r"(r[2]), "=r"(r[3]) : "r"(addr));
}

__device__ __forceinline__ void mma_f16(float* c, const unsigned* a, unsigned b0, unsigned b1) {
    asm volatile(
        "mma.sync.aligned.m16n8k16.row.col.f32.f16.f16.f32 "
        "{%0,%1,%2,%3},{%4,%5,%6,%7},{%8,%9},{%0,%1,%2,%3};"
        : "+f"(c[0]), "+f"(c[1]), "+f"(c[2]), "+f"(c[3])
        : "r"(a[0]), "r"(a[1]), "r"(a[2]), "r"(a[3]), "r"(b0), "r"(b1));
}

__device__ __forceinline__ float tanh_ap(float x) {
    float t;
    asm("tanh.approx.f32 %0, %1;" : "=f"(t) : "f"(x));
    return t;
}

__global__ __launch_bounds__(THREADS, 3)
void swr_kernel(const float* __restrict__ x, const float* __restrict__ W1,
                const float* __restrict__ b1, const float* __restrict__ W2,
                const float* __restrict__ b2, float* __restrict__ out)
{
    extern __shared__ char sm[];
    float2* bw   = (float2*)(sm + BW_OFF);
    float*  part = (float*)(sm + PART_OFF);

    const int tid = threadIdx.x;
    const int R0  = blockIdx.x * ROWS;
    const int o0  = blockIdx.y * OPB;

    // ---- stage x as fp16: [8 kc][128 rows][16B] ----
    #pragma unroll
    for (int i = 0; i < 4; i++) {
        int idx = tid + i * THREADS;             // 1024 chunks
        int kc = idx >> 7, r = idx & 127;
        const float* p = x + (size_t)(R0 + r) * KDIM + kc * 8;
        float4 v0 = *(const float4*)p;
        float4 v1 = *(const float4*)(p + 4);
        uint4 u;
        u.x = pack_f16x2(v0.x, v0.y); u.y = pack_f16x2(v0.z, v0.w);
        u.z = pack_f16x2(v1.x, v1.y); u.w = pack_f16x2(v1.z, v1.w);
        *(uint4*)(sm + XS_OFF + kc * XCHUNK + r * 16) = u;
    }

    // ---- stage W1 as fp16: [8 kc][256 rows (2 o x 128 h)][16B] ----
    #pragma unroll
    for (int i = 0; i < 8; i++) {
        int idx = tid + i * THREADS;             // 2048 chunks
        int kc = idx >> 8, nr = idx & 255;
        int ol = nr >> 7, h = nr & 127;
        const float* p = W1 + ((size_t)(o0 + ol) * HDIM + h) * KDIM + kc * 8;
        float4 v0 = *(const float4*)p;
        float4 v1 = *(const float4*)(p + 4);
        uint4 u;
        u.x = pack_f16x2(v0.x, v0.y); u.y = pack_f16x2(v0.z, v0.w);
        u.z = pack_f16x2(v1.x, v1.y); u.w = pack_f16x2(v1.z, v1.w);
        *(uint4*)(sm + WS_OFF + kc * WCHUNK + nr * 16) = u;
    }

    // ---- stage (0.5*b1, w2) pairs ----
    {
        int ol = tid >> 7, h = tid & 127;
        bw[tid] = make_float2(0.5f * b1[(o0 + ol) * HDIM + h], W2[(o0 + ol) * HDIM + h]);
    }
    __syncthreads();

    const int w    = tid >> 5;
    const int lane = tid & 31;
    const int rg   = w >> 1;                 // row-group 0..3 (32 rows)
    const int cg   = w & 1;                  // col-half 0..1 (64 h)
    const int rw   = rg * 32;
    const int gid  = lane >> 2;
    const int tig  = lane & 3;

    const uint32_t smb = smem_u32(sm);

    // A: lanes 0-15 rows rw+(L&15) k-lo chunk; lanes 16-31 same rows k-hi
    const uint32_t pA = smb + XS_OFF + (uint32_t)(lane >> 4) * XCHUNK
                      + (uint32_t)(rw + (lane & 15)) * 16;
    // B: m0/m1 = n-rows 0-7 (k-lo/k-hi), m2/m3 = n-rows 8-15
    const uint32_t pB = smb + WS_OFF + (uint32_t)((lane >> 3) & 1) * WCHUNK
                      + (uint32_t)(((lane >> 4) * 8) + (lane & 7)) * 16;

    // ---- hoist A fragments for m32 x k64 (shared across ol & n-chunks) ----
    unsigned a[4][2][4];                     // [k-step][m-tile][frag]
    #pragma unroll
    for (int kk = 0; kk < 4; ++kk) {
        ldsm4(pA + (uint32_t)kk * (2 * XCHUNK), a[kk][0]);
        ldsm4(pA + (uint32_t)kk * (2 * XCHUNK) + 256, a[kk][1]);   // rows +16
    }

    #pragma unroll
    for (int ol = 0; ol < OPB; ++ol) {
        float r[4] = {0.f, 0.f, 0.f, 0.f};   // rows rw+gid, +8, +16, +24

        #pragma unroll
        for (int ch = 0; ch < 2; ++ch) {     // two n32 chunks of this warp's n64
            float c[2][4][4];                // [m-tile][n-tile][frag]
            #pragma unroll
            for (int mt = 0; mt < 2; ++mt)
                #pragma unroll
                for (int n = 0; n < 4; ++n) {
                    c[mt][n][0] = 0.f; c[mt][n][1] = 0.f;
                    c[mt][n][2] = 0.f; c[mt][n][3] = 0.f;
                }

            const uint32_t pBo = pB + (uint32_t)(ol * 128 + cg * 64 + ch * 32) * 16;

            #pragma unroll
            for (int kk = 0; kk < 4; ++kk) {
                const uint32_t pBk = pBo + (uint32_t)kk * (2 * WCHUNK);
                #pragma unroll
                for (int p = 0; p < 2; ++p) {
                    unsigned b[4];           // (b0,b1) n-tile 2p ; n-tile 2p+1
                    ldsm4(pBk + (uint32_t)p * 256, b);
                    mma_f16(c[0][2 * p],     a[kk][0], b[0], b[1]);
                    mma_f16(c[0][2 * p + 1], a[kk][0], b[2], b[3]);
                    mma_f16(c[1][2 * p],     a[kk][1], b[0], b[1]);
                    mma_f16(c[1][2 * p + 1], a[kk][1], b[2], b[3]);
                }
            }

            // ---- fused epilogue: silu (tanh.approx) + W2 reduction ----
            const float4* bwp = (const float4*)(bw + ol * HDIM + cg * 64 + ch * 32 + tig * 2);
            #pragma unroll
            for (int n = 0; n < 4; ++n) {
                float4 q = bwp[n * 4];       // (0.5*b1[h0], w2[h0], 0.5*b1[h1], w2[h1])
                #pragma unroll
                for (int mt = 0; mt < 2; ++mt) {
                    float h00 = fmaf(c[mt][n][0], 0.5f, q.x);
                    float h01 = fmaf(c[mt][n][1], 0.5f, q.z);
                    float h10 = fmaf(c[mt][n][2], 0.5f, q.x);
                    float h11 = fmaf(c[mt][n][3], 0.5f, q.z);
                    r[2 * mt]     = fmaf(fmaf(h00, tanh_ap(h00), h00), q.y, r[2 * mt]);
                    r[2 * mt]     = fmaf(fmaf(h01, tanh_ap(h01), h01), q.w, r[2 * mt]);
                    r[2 * mt + 1] = fmaf(fmaf(h10, tanh_ap(h10), h10), q.y, r[2 * mt + 1]);
                    r[2 * mt + 1] = fmaf(fmaf(h11, tanh_ap(h11), h11), q.w, r[2 * mt + 1]);
                }
            }
        }

        #pragma unroll
        for (int t = 0; t < 4; ++t) {
            r[t] += __shfl_xor_sync(0xffffffffu, r[t], 1);
            r[t] += __shfl_xor_sync(0xffffffffu, r[t], 2);
        }
        if (tig == 0) {
            float* dst = part + (ol * 2 + cg) * 128 + rw + gid;
            dst[0]  = r[0];
            dst[8]  = r[1];
            dst[16] = r[2];
            dst[24] = r[3];
        }
    }

    __syncthreads();

    // ---- combine cg halves, add b2, coalesced float2 store ----
    if (tid < 128) {
        float2 o;
        o.x = part[tid]       + part[128 + tid] + __ldg(b2 + o0);
        o.y = part[256 + tid] + part[384 + tid] + __ldg(b2 + o0 + 1);
        *(float2*)(out + (size_t)(R0 + tid) * ODIM + o0) = o;
    }
}

extern "C" void kernel_launch(void* const* d_in, const int* in_sizes, int n_in,
                              void* d_out, int out_size)
{
    const float* x  = (const float*)d_in[0];  // [NC, 64]
    const float* W1 = (const float*)d_in[1];  // [32, 128, 64]
    const float* b1 = (const float*)d_in[2];  // [32, 128]
    const float* W2 = (const float*)d_in[3];  // [32, 128]
    const float* b2 = (const float*)d_in[4];  // [32]
    float* out = (float*)d_out;               // [NC, 32]

    const int NC = in_sizes[0] / KDIM;        // 131072

    cudaFuncSetAttribute(swr_kernel, cudaFuncAttributeMaxDynamicSharedMemorySize, SMEM_BYTES);

    dim3 grid(NC / ROWS, ODIM / OPB);         // (1024, 16)
    swr_kernel<<<grid, THREADS, SMEM_BYTES>>>(x, W1, b1, W2, b2, out);
}

// round 11
// speedup vs baseline: 2.9431x; 2.9431x over previous
#include <cuda_runtime.h>
#include <cuda_fp16.h>
#include <cstdint>
#include <cstddef>

// ScalarWaveletRecombiner: out[n,o] = W2[o]·silu(W1[o]·x[n] + b1[o]) + b2[o]
// x:[NC,64] W1:[32,128,64] b1:[32,128] W2:[32,128] b2:[32] -> out:[NC,32]
//
// v7: two-kernel scheme.
//  K1: convert x,W1 -> fp16 scratch, pre-laid in smem tile order.
//  K2: fp16 m16n8k16 mma, 512 thr (16 warps m32n64), OPB=4 MLPs, persistent
//      over RT=4 row-tiles; W1 cp.async'd once, x double-buffered cp.async
//      overlapped with compute. Epilogue: silu(tanh.approx) + W2 reduce.

#define KDIM 64
#define HDIM 128
#define ODIM 32
#define OPB 4
#define ROWS 256
#define RT 4
#define THREADS 512
#define NC_TOT 131072
#define NTILES (NC_TOT / ROWS)          // 512

// fp16 scratch, pre-laid:
//  g_xh: [512 tiles][8 kc][256 rows][8 fp16]  = 16 MB
//  g_wh: [8 og][8 kc][512 nr(4 o x 128 h)][8 fp16] = 512 KB
__device__ uint4 g_xh[NTILES * 8 * 256];
__device__ uint4 g_wh[8 * 8 * 512];

// smem layout (bytes), main kernel
#define WS_OFF    0         // fp16 W1 [8 kc][512 nr][16B]      = 65536
#define XS_OFF    65536     // fp16 x, 2 bufs [8 kc][256 r][16B] = 65536
#define BW_OFF    131072    // float2 (0.5*b1, w2) [4][128]      = 4096
#define PART_OFF  135168    // float [8][256]                    = 8192
#define SMEM_BYTES 143360

#define XCHUNK 4096         // 256 rows * 16B (kc stride in x buf)
#define XBUF   32768
#define WCHUNK 8192         // 512 rows * 16B (kc stride in W buf)

__device__ __forceinline__ unsigned pack_f16x2(float lo, float hi) {
    unsigned r;
    asm("cvt.rn.f16x2.f32 %0, %2, %1;" : "=r"(r) : "f"(lo), "f"(hi));
    return r;
}

__device__ __forceinline__ uint32_t smem_u32(const void* p) {
    uint32_t a;
    asm("{ .reg .u64 t; cvta.to.shared.u64 t, %1; cvt.u32.u64 %0, t; }" : "=r"(a) : "l"(p));
    return a;
}

__device__ __forceinline__ void cp16(uint32_t dst, const void* src) {
    asm volatile("cp.async.cg.shared.global [%0], [%1], 16;" :: "r"(dst), "l"(src));
}
#define CP_COMMIT() asm volatile("cp.async.commit_group;" ::: "memory")
#define CP_WAIT0()  asm volatile("cp.async.wait_group 0;" ::: "memory")

__device__ __forceinline__ void ldsm4(uint32_t addr, unsigned* r) {
    asm volatile("ldmatrix.sync.aligned.m8n8.x4.shared.b16 {%0,%1,%2,%3}, [%4];"
                 : "=r"(r[0]), "=r"(r[1]), "=r"(r[2]), "=r"(r[3]) : "r"(addr));
}

__device__ __forceinline__ void mma_f16(float* c, const unsigned* a, unsigned b0, unsigned b1) {
    asm volatile(
        "mma.sync.aligned.m16n8k16.row.col.f32.f16.f16.f32 "
        "{%0,%1,%2,%3},{%4,%5,%6,%7},{%8,%9},{%0,%1,%2,%3};"
        : "+f"(c[0]), "+f"(c[1]), "+f"(c[2]), "+f"(c[3])
        : "r"(a[0]), "r"(a[1]), "r"(a[2]), "r"(a[3]), "r"(b0), "r"(b1));
}

__device__ __forceinline__ float tanh_ap(float x) {
    float t;
    asm("tanh.approx.f32 %0, %1;" : "=f"(t) : "f"(x));
    return t;
}

// ---------------- kernel 1: convert to fp16 scratch ----------------
__global__ __launch_bounds__(256)
void cvt_kernel(const float* __restrict__ x, const float* __restrict__ W1)
{
    int b = blockIdx.x;
    if (b < 4096) {
        // x: 1,048,576 chunks; 256 per block
        int c = b * 256 + threadIdx.x;
        int tile = c >> 11, kc = (c >> 8) & 7, r = c & 255;
        const float* p = x + ((size_t)(tile * 256 + r) * KDIM) + kc * 8;
        float4 v0 = *(const float4*)p;
        float4 v1 = *(const float4*)(p + 4);
        uint4 u;
        u.x = pack_f16x2(v0.x, v0.y); u.y = pack_f16x2(v0.z, v0.w);
        u.z = pack_f16x2(v1.x, v1.y); u.w = pack_f16x2(v1.z, v1.w);
        g_xh[c] = u;
    } else {
        // W1: 32768 chunks; 256 per block, 128 blocks
        int c = (b - 4096) * 256 + threadIdx.x;
        int og = c >> 12, kc = (c >> 9) & 7, nr = c & 511;
        int o = og * 4 + (nr >> 7), h = nr & 127;
        const float* p = W1 + ((size_t)o * HDIM + h) * KDIM + kc * 8;
        float4 v0 = *(const float4*)p;
        float4 v1 = *(const float4*)(p + 4);
        uint4 u;
        u.x = pack_f16x2(v0.x, v0.y); u.y = pack_f16x2(v0.z, v0.w);
        u.z = pack_f16x2(v1.x, v1.y); u.w = pack_f16x2(v1.z, v1.w);
        g_wh[c] = u;
    }
}

// ---------------- kernel 2: main fused MLP ----------------
__global__ __launch_bounds__(THREADS, 1)
void swr_kernel(const float* __restrict__ b1, const float* __restrict__ W2,
                const float* __restrict__ b2, float* __restrict__ out)
{
    extern __shared__ char sm[];
    float2* bw   = (float2*)(sm + BW_OFF);
    float*  part = (float*)(sm + PART_OFF);

    const int tid   = threadIdx.x;
    const int og    = blockIdx.y;
    const int o0    = og * OPB;
    const int tile0 = blockIdx.x * RT;

    const uint32_t smb = smem_u32(sm);

    // ---- cp.async: W1 slice (64 KB) + x tile0 (32 KB), one group ----
    {
        const uint4* gw = g_wh + (size_t)og * 4096;
        #pragma unroll
        for (int i = 0; i < 8; i++) {
            int c = tid + i * THREADS;
            cp16(smb + WS_OFF + c * 16, gw + c);
        }
        const uint4* gx = g_xh + (size_t)tile0 * 2048;
        #pragma unroll
        for (int i = 0; i < 4; i++) {
            int c = tid + i * THREADS;
            cp16(smb + XS_OFF + c * 16, gx + c);
        }
        CP_COMMIT();
    }

    // ---- stage (0.5*b1, w2) pairs (512 entries, regular loads) ----
    {
        int ol = tid >> 7, h = tid & 127;
        bw[tid] = make_float2(0.5f * b1[(o0 + ol) * HDIM + h], W2[(o0 + ol) * HDIM + h]);
    }
    float b2v[OPB];
    #pragma unroll
    for (int ol = 0; ol < OPB; ++ol) b2v[ol] = __ldg(b2 + o0 + ol);

    const int w    = tid >> 5;
    const int lane = tid & 31;
    const int rg   = w >> 1;                 // 8 row-groups (32 rows each)
    const int cg   = w & 1;                  // 2 col-groups (64 h each)
    const int rw   = rg * 32;
    const int gid  = lane >> 2;
    const int tig  = lane & 3;

    // A ldmatrix lane addr offset within x buffer
    const uint32_t offA = (uint32_t)(lane >> 4) * XCHUNK
                        + (uint32_t)(rw + (lane & 15)) * 16;
    // B ldmatrix lane base
    const uint32_t pB = smb + WS_OFF + (uint32_t)((lane >> 3) & 1) * WCHUNK
                      + (uint32_t)((cg * 64) + ((lane >> 4) * 8) + (lane & 7)) * 16;

    #pragma unroll 1
    for (int it = 0; it < RT; ++it) {
        CP_WAIT0();
        __syncthreads();

        // issue next x tile into the other buffer (overlaps with compute)
        if (it + 1 < RT) {
            const uint4* gx = g_xh + (size_t)(tile0 + it + 1) * 2048;
            const uint32_t xdst = smb + XS_OFF + (uint32_t)((it + 1) & 1) * XBUF;
            #pragma unroll
            for (int i = 0; i < 4; i++) {
                int c = tid + i * THREADS;
                cp16(xdst + c * 16, gx + c);
            }
            CP_COMMIT();
        }

        // ---- hoist A fragments for this tile (m32 x k64) ----
        const uint32_t pA = smb + XS_OFF + (uint32_t)(it & 1) * XBUF + offA;
        unsigned a[4][2][4];
        #pragma unroll
        for (int kk = 0; kk < 4; ++kk) {
            ldsm4(pA + (uint32_t)kk * (2 * XCHUNK), a[kk][0]);
            ldsm4(pA + (uint32_t)kk * (2 * XCHUNK) + 256, a[kk][1]);  // rows +16
        }

        #pragma unroll 1
        for (int ol = 0; ol < OPB; ++ol) {
            float c[2][8][4];
            #pragma unroll
            for (int n = 0; n < 8; ++n)
                #pragma unroll
                for (int mt = 0; mt < 2; ++mt) {
                    c[mt][n][0] = 0.f; c[mt][n][1] = 0.f;
                    c[mt][n][2] = 0.f; c[mt][n][3] = 0.f;
                }

            const uint32_t pBo = pB + (uint32_t)ol * 2048;   // ol*128 rows*16B

            #pragma unroll
            for (int kk = 0; kk < 4; ++kk) {
                const uint32_t pBk = pBo + (uint32_t)kk * (2 * WCHUNK);
                #pragma unroll
                for (int p = 0; p < 4; ++p) {
                    unsigned b[4];
                    ldsm4(pBk + (uint32_t)p * 256, b);
                    mma_f16(c[0][2 * p],     a[kk][0], b[0], b[1]);
                    mma_f16(c[0][2 * p + 1], a[kk][0], b[2], b[3]);
                    mma_f16(c[1][2 * p],     a[kk][1], b[0], b[1]);
                    mma_f16(c[1][2 * p + 1], a[kk][1], b[2], b[3]);
                }
            }

            // ---- fused epilogue: silu (tanh.approx) + W2 reduction ----
            float acc[2][2] = {{0.f, 0.f}, {0.f, 0.f}};
            const float4* bwp = (const float4*)(bw + ol * HDIM + cg * 64 + tig * 2);
            #pragma unroll
            for (int n = 0; n < 8; ++n) {
                float4 q = bwp[n * 4];  // (0.5*b1[h0], w2[h0], 0.5*b1[h1], w2[h1])
                #pragma unroll
                for (int mt = 0; mt < 2; ++mt) {
                    float h00 = fmaf(c[mt][n][0], 0.5f, q.x);
                    float h01 = fmaf(c[mt][n][1], 0.5f, q.z);
                    float h10 = fmaf(c[mt][n][2], 0.5f, q.x);
                    float h11 = fmaf(c[mt][n][3], 0.5f, q.z);
                    acc[mt][0] = fmaf(fmaf(h00, tanh_ap(h00), h00), q.y, acc[mt][0]);
                    acc[mt][0] = fmaf(fmaf(h01, tanh_ap(h01), h01), q.w, acc[mt][0]);
                    acc[mt][1] = fmaf(fmaf(h10, tanh_ap(h10), h10), q.y, acc[mt][1]);
                    acc[mt][1] = fmaf(fmaf(h11, tanh_ap(h11), h11), q.w, acc[mt][1]);
                }
            }

            #pragma unroll
            for (int mt = 0; mt < 2; ++mt)
                #pragma unroll
                for (int r = 0; r < 2; ++r) {
                    float v = acc[mt][r];
                    v += __shfl_xor_sync(0xffffffffu, v, 1);
                    v += __shfl_xor_sync(0xffffffffu, v, 2);
                    if (tig == 0)
                        part[(ol * 2 + cg) * 256 + rw + mt * 16 + r * 8 + gid] = v;
                }
        }

        __syncthreads();

        // ---- combine cg halves, add b2, coalesced float4 store ----
        if (tid < 256) {
            float4 o;
            float* po = (float*)&o;
            #pragma unroll
            for (int ol = 0; ol < OPB; ++ol)
                po[ol] = part[(ol * 2) * 256 + tid] + part[(ol * 2 + 1) * 256 + tid]
                       + b2v[ol];
            *(float4*)(out + (size_t)((tile0 + it) * ROWS + tid) * ODIM + o0) = o;
        }
        // next iteration's first __syncthreads orders part reuse
    }
}

extern "C" void kernel_launch(void* const* d_in, const int* in_sizes, int n_in,
                              void* d_out, int out_size)
{
    const float* x  = (const float*)d_in[0];  // [NC, 64]
    const float* W1 = (const float*)d_in[1];  // [32, 128, 64]
    const float* b1 = (const float*)d_in[2];  // [32, 128]
    const float* W2 = (const float*)d_in[3];  // [32, 128]
    const float* b2 = (const float*)d_in[4];  // [32]
    float* out = (float*)d_out;               // [NC, 32]

    cvt_kernel<<<4096 + 128, 256>>>(x, W1);

    cudaFuncSetAttribute(swr_kernel, cudaFuncAttributeMaxDynamicSharedMemorySize, SMEM_BYTES);
    dim3 grid(NTILES / RT, 8);                // (128, 8)
    swr_kernel<<<grid, THREADS, SMEM_BYTES>>>(b1, W2, b2, out);
}

// round 12
// speedup vs baseline: 3.2228x; 1.0950x over previous
#include <cuda_runtime.h>
#include <cuda_fp16.h>
#include <cstdint>
#include <cstddef>

// ScalarWaveletRecombiner: out[n,o] = W2[o]·silu(W1[o]·x[n] + b1[o]) + b2[o]
// x:[NC,64] W1:[32,128,64] b1:[32,128] W2:[32,128] b2:[32] -> out:[NC,32]
//
// v8: R11 + software pipelining of MMA vs epilogue.
//  K1: convert x,W1 -> fp16 scratch in smem tile order.
//  K2: fp16 m16n8k16 mma, 512 thr, OPB=4, RT=4 row-tiles, cp.async x double
//      buffer. Each warp's work split into 8 m32n32 chunks; MMA(chunk q)
//      issued before epilogue(chunk q-1) -> tensor overlaps MUFU/FMA.

#define KDIM 64
#define HDIM 128
#define ODIM 32
#define OPB 4
#define ROWS 256
#define RT 4
#define THREADS 512
#define NC_TOT 131072
#define NTILES (NC_TOT / ROWS)          // 512

// fp16 scratch, pre-laid:
//  g_xh: [512 tiles][8 kc][256 rows][8 fp16]  = 16 MB
//  g_wh: [8 og][8 kc][512 nr(4 o x 128 h)][8 fp16] = 512 KB
__device__ uint4 g_xh[NTILES * 8 * 256];
__device__ uint4 g_wh[8 * 8 * 512];

// smem layout (bytes), main kernel
#define WS_OFF    0         // fp16 W1 [8 kc][512 nr][16B]       = 65536
#define XS_OFF    65536     // fp16 x, 2 bufs [8 kc][256 r][16B] = 65536
#define BW_OFF    131072    // float2 (0.5*b1, w2) [4][128]      = 4096
#define PART_OFF  135168    // float [8][256]                    = 8192
#define SMEM_BYTES 143360

#define XCHUNK 4096         // 256 rows * 16B (kc stride in x buf)
#define XBUF   32768
#define WCHUNK 8192         // 512 rows * 16B (kc stride in W buf)

__device__ __forceinline__ unsigned pack_f16x2(float lo, float hi) {
    unsigned r;
    asm("cvt.rn.f16x2.f32 %0, %2, %1;" : "=r"(r) : "f"(lo), "f"(hi));
    return r;
}

__device__ __forceinline__ uint32_t smem_u32(const void* p) {
    uint32_t a;
    asm("{ .reg .u64 t; cvta.to.shared.u64 t, %1; cvt.u32.u64 %0, t; }" : "=r"(a) : "l"(p));
    return a;
}

__device__ __forceinline__ void cp16(uint32_t dst, const void* src) {
    asm volatile("cp.async.cg.shared.global [%0], [%1], 16;" :: "r"(dst), "l"(src));
}
#define CP_COMMIT() asm volatile("cp.async.commit_group;" ::: "memory")
#define CP_WAIT0()  asm volatile("cp.async.wait_group 0;" ::: "memory")

__device__ __forceinline__ void ldsm4(uint32_t addr, unsigned* r) {
    asm volatile("ldmatrix.sync.aligned.m8n8.x4.shared.b16 {%0,%1,%2,%3}, [%4];"
                 : "=r"(r[0]), "=r"(r[1]), "=r"(r[2]), "=r"(r[3]) : "r"(addr));
}

__device__ __forceinline__ void mma_f16(float* c, const unsigned* a, unsigned b0, unsigned b1) {
    asm volatile(
        "mma.sync.aligned.m16n8k16.row.col.f32.f16.f16.f32 "
        "{%0,%1,%2,%3},{%4,%5,%6,%7},{%8,%9},{%0,%1,%2,%3};"
        : "+f"(c[0]), "+f"(c[1]), "+f"(c[2]), "+f"(c[3])
        : "r"(a[0]), "r"(a[1]), "r"(a[2]), "r"(a[3]), "r"(b0), "r"(b1));
}

__device__ __forceinline__ float tanh_ap(float x) {
    float t;
    asm("tanh.approx.f32 %0, %1;" : "=f"(t) : "f"(x));
    return t;
}

// ---------------- kernel 1: convert to fp16 scratch ----------------
__global__ __launch_bounds__(256)
void cvt_kernel(const float* __restrict__ x, const float* __restrict__ W1)
{
    int b = blockIdx.x;
    if (b < 4096) {
        int c = b * 256 + threadIdx.x;
        int tile = c >> 11, kc = (c >> 8) & 7, r = c & 255;
        const float* p = x + ((size_t)(tile * 256 + r) * KDIM) + kc * 8;
        float4 v0 = *(const float4*)p;
        float4 v1 = *(const float4*)(p + 4);
        uint4 u;
        u.x = pack_f16x2(v0.x, v0.y); u.y = pack_f16x2(v0.z, v0.w);
        u.z = pack_f16x2(v1.x, v1.y); u.w = pack_f16x2(v1.z, v1.w);
        g_xh[c] = u;
    } else {
        int c = (b - 4096) * 256 + threadIdx.x;
        int og = c >> 12, kc = (c >> 9) & 7, nr = c & 511;
        int o = og * 4 + (nr >> 7), h = nr & 127;
        const float* p = W1 + ((size_t)o * HDIM + h) * KDIM + kc * 8;
        float4 v0 = *(const float4*)p;
        float4 v1 = *(const float4*)(p + 4);
        uint4 u;
        u.x = pack_f16x2(v0.x, v0.y); u.y = pack_f16x2(v0.z, v0.w);
        u.z = pack_f16x2(v1.x, v1.y); u.w = pack_f16x2(v1.z, v1.w);
        g_wh[c] = u;
    }
}

// ---------------- kernel 2: main fused MLP ----------------
__global__ __launch_bounds__(THREADS, 1)
void swr_kernel(const float* __restrict__ b1, const float* __restrict__ W2,
                const float* __restrict__ b2, float* __restrict__ out)
{
    extern __shared__ char sm[];
    float2* bw   = (float2*)(sm + BW_OFF);
    float*  part = (float*)(sm + PART_OFF);

    const int tid   = threadIdx.x;
    const int og    = blockIdx.y;
    const int o0    = og * OPB;
    const int tile0 = blockIdx.x * RT;

    const uint32_t smb = smem_u32(sm);

    // ---- cp.async: W1 slice (64 KB) + x tile0 (32 KB), one group ----
    {
        const uint4* gw = g_wh + (size_t)og * 4096;
        #pragma unroll
        for (int i = 0; i < 8; i++) {
            int c = tid + i * THREADS;
            cp16(smb + WS_OFF + c * 16, gw + c);
        }
        const uint4* gx = g_xh + (size_t)tile0 * 2048;
        #pragma unroll
        for (int i = 0; i < 4; i++) {
            int c = tid + i * THREADS;
            cp16(smb + XS_OFF + c * 16, gx + c);
        }
        CP_COMMIT();
    }

    // ---- stage (0.5*b1, w2) pairs ----
    {
        int ol = tid >> 7, h = tid & 127;
        bw[tid] = make_float2(0.5f * b1[(o0 + ol) * HDIM + h], W2[(o0 + ol) * HDIM + h]);
    }
    float b2v[OPB];
    #pragma unroll
    for (int ol = 0; ol < OPB; ++ol) b2v[ol] = __ldg(b2 + o0 + ol);

    const int w    = tid >> 5;
    const int lane = tid & 31;
    const int rg   = w >> 1;                 // 8 row-groups (32 rows each)
    const int cg   = w & 1;                  // 2 col-groups (64 h each)
    const int rw   = rg * 32;
    const int gid  = lane >> 2;
    const int tig  = lane & 3;

    const uint32_t offA = (uint32_t)(lane >> 4) * XCHUNK
                        + (uint32_t)(rw + (lane & 15)) * 16;
    const uint32_t pB = smb + WS_OFF + (uint32_t)((lane >> 3) & 1) * WCHUNK
                      + (uint32_t)((cg * 64) + ((lane >> 4) * 8) + (lane & 7)) * 16;

    #pragma unroll 1
    for (int it = 0; it < RT; ++it) {
        CP_WAIT0();
        __syncthreads();

        // issue next x tile into the other buffer (overlaps with compute)
        if (it + 1 < RT) {
            const uint4* gx = g_xh + (size_t)(tile0 + it + 1) * 2048;
            const uint32_t xdst = smb + XS_OFF + (uint32_t)((it + 1) & 1) * XBUF;
            #pragma unroll
            for (int i = 0; i < 4; i++) {
                int c = tid + i * THREADS;
                cp16(xdst + c * 16, gx + c);
            }
            CP_COMMIT();
        }

        // ---- hoist A fragments for this tile (m32 x k64) ----
        const uint32_t pA = smb + XS_OFF + (uint32_t)(it & 1) * XBUF + offA;
        unsigned a[4][2][4];
        #pragma unroll
        for (int kk = 0; kk < 4; ++kk) {
            ldsm4(pA + (uint32_t)kk * (2 * XCHUNK), a[kk][0]);
            ldsm4(pA + (uint32_t)kk * (2 * XCHUNK) + 256, a[kk][1]);  // rows +16
        }

        // ---- software-pipelined chunk loop: 8 chunks of m32n32 ----
        // chunk q: ol = q>>1, half = q&1. MMA(q) issued before epilogue(q-1).
        float cbuf[2][32];                   // [buf][(mt*4+nt)*4 + j]
        float r[4] = {0.f, 0.f, 0.f, 0.f};   // row sums rows rw+gid+{0,8,16,24}

        #pragma unroll
        for (int q = 0; q < 9; ++q) {
            // ---- MMA of chunk q into cbuf[q&1] ----
            if (q < 8) {
                float* cc = cbuf[q & 1];
                #pragma unroll
                for (int i = 0; i < 32; i++) cc[i] = 0.f;

                const int ol = q >> 1, hf = q & 1;
                const uint32_t pBo = pB + (uint32_t)(ol * 128 + hf * 32) * 16;
                #pragma unroll
                for (int kk = 0; kk < 4; ++kk) {
                    const uint32_t pBk = pBo + (uint32_t)kk * (2 * WCHUNK);
                    #pragma unroll
                    for (int p = 0; p < 2; ++p) {
                        unsigned b[4];       // 2 n8-tiles
                        ldsm4(pBk + (uint32_t)p * 256, b);
                        mma_f16(cc + (0 * 4 + 2 * p) * 4,     a[kk][0], b[0], b[1]);
                        mma_f16(cc + (0 * 4 + 2 * p + 1) * 4, a[kk][0], b[2], b[3]);
                        mma_f16(cc + (1 * 4 + 2 * p) * 4,     a[kk][1], b[0], b[1]);
                        mma_f16(cc + (1 * 4 + 2 * p + 1) * 4, a[kk][1], b[2], b[3]);
                    }
                }
            }

            // ---- epilogue of chunk q-1 from cbuf[(q-1)&1] ----
            if (q > 0) {
                const int qq = q - 1, ol = qq >> 1, hf = qq & 1;
                const float* cp = cbuf[qq & 1];
                const float4* bwp =
                    (const float4*)(bw + ol * HDIM + cg * 64 + hf * 32 + tig * 2);
                #pragma unroll
                for (int nt = 0; nt < 4; ++nt) {
                    float4 qv = bwp[nt * 4]; // (0.5*b1[h0], w2[h0], 0.5*b1[h1], w2[h1])
                    #pragma unroll
                    for (int mt = 0; mt < 2; ++mt) {
                        const float* cc = cp + (mt * 4 + nt) * 4;
                        float h00 = fmaf(cc[0], 0.5f, qv.x);
                        float h01 = fmaf(cc[1], 0.5f, qv.z);
                        float h10 = fmaf(cc[2], 0.5f, qv.x);
                        float h11 = fmaf(cc[3], 0.5f, qv.z);
                        r[2 * mt]     = fmaf(fmaf(h00, tanh_ap(h00), h00), qv.y, r[2 * mt]);
                        r[2 * mt]     = fmaf(fmaf(h01, tanh_ap(h01), h01), qv.w, r[2 * mt]);
                        r[2 * mt + 1] = fmaf(fmaf(h10, tanh_ap(h10), h10), qv.y, r[2 * mt + 1]);
                        r[2 * mt + 1] = fmaf(fmaf(h11, tanh_ap(h11), h11), qv.w, r[2 * mt + 1]);
                    }
                }
                if (hf == 1) {               // finished this ol: reduce & store
                    #pragma unroll
                    for (int t = 0; t < 4; ++t) {
                        r[t] += __shfl_xor_sync(0xffffffffu, r[t], 1);
                        r[t] += __shfl_xor_sync(0xffffffffu, r[t], 2);
                    }
                    if (tig == 0) {
                        float* dst = part + (ol * 2 + cg) * 256 + rw + gid;
                        dst[0]  = r[0];
                        dst[8]  = r[1];
                        dst[16] = r[2];
                        dst[24] = r[3];
                    }
                    r[0] = r[1] = r[2] = r[3] = 0.f;
                }
            }
        }

        __syncthreads();

        // ---- combine cg halves, add b2, coalesced float4 store ----
        if (tid < 256) {
            float4 o;
            float* po = (float*)&o;
            #pragma unroll
            for (int ol = 0; ol < OPB; ++ol)
                po[ol] = part[(ol * 2) * 256 + tid] + part[(ol * 2 + 1) * 256 + tid]
                       + b2v[ol];
            *(float4*)(out + (size_t)((tile0 + it) * ROWS + tid) * ODIM + o0) = o;
        }
    }
}

extern "C" void kernel_launch(void* const* d_in, const int* in_sizes, int n_in,
                              void* d_out, int out_size)
{
    const float* x  = (const float*)d_in[0];  // [NC, 64]
    const float* W1 = (const float*)d_in[1];  // [32, 128, 64]
    const float* b1 = (const float*)d_in[2];  // [32, 128]
    const float* W2 = (const float*)d_in[3];  // [32, 128]
    const float* b2 = (const float*)d_in[4];  // [32]
    float* out = (float*)d_out;               // [NC, 32]

    cvt_kernel<<<4096 + 128, 256>>>(x, W1);

    cudaFuncSetAttribute(swr_kernel, cudaFuncAttributeMaxDynamicSharedMemorySize, SMEM_BYTES);
    dim3 grid(NTILES / RT, 8);                // (128, 8)
    swr_kernel<<<grid, THREADS, SMEM_BYTES>>>(b1, W2, b2, out);
}